// round 7
// baseline (speedup 1.0000x reference)
#include <cuda_runtime.h>
#include <cstdint>

#define NN 100000
#define NE 1600000
#define DIN 128

#define CHUNK 1024
#define NBLK ((NN + CHUNK - 1) / CHUNK)   // 98 scan blocks

// ---------------- scratch (static __device__, no allocation) ----------------
__device__ __align__(16) float g_deg[NN];       // degree -> deg_inv_sqrt (in place)
__device__ int   g_cnt[NN];                     // in-degree counts (edges only)
__device__ int   g_cur[NN];                     // bucket cursors
__device__ int   g_rowstart[NN + 1];            // CSR row offsets (by dst)
__device__ int   g_bsum[NBLK];                  // per-chunk edge-count sums
__device__ int   g_bpre[NBLK];                  // exclusive prefix of chunk sums
struct __align__(8) Edge { int src; float nrm; };
__device__ Edge  g_edge[NE];                    // CSR-sorted (src, norm) records
__device__ __align__(16) float g_h[(size_t)NN * 128];   // transformed features
__device__ __align__(16) float g_a[(size_t)NN * 128];   // activation ping
__device__ __align__(16) float g_b[(size_t)NN * 128];   // activation pong

template <int SEL>
__device__ __forceinline__ float* buf() {
    if constexpr (SEL == 0) return g_h;
    else if constexpr (SEL == 1) return g_a;
    else return g_b;
}

// ---------------- packed f32x2 helpers ----------------
__device__ __forceinline__ void ffma2(uint64_t& d, uint64_t a, uint64_t b) {
    asm("fma.rn.f32x2 %0, %1, %2, %0;" : "+l"(d) : "l"(a), "l"(b));
}
__device__ __forceinline__ void unpack2(uint64_t v, float& lo, float& hi) {
    asm("mov.b64 {%0, %1}, %2;" : "=f"(lo), "=f"(hi) : "l"(v));
}

// ---------------- preamble ----------------
__global__ void k_init() {
    int i = blockIdx.x * blockDim.x + threadIdx.x;
    if (i < NN) { g_deg[i] = 1.0f; g_cnt[i] = 0; g_cur[i] = 0; }
}

// edge_index delivered as int32: [0..NE) = src, [NE..2NE) = dst. 4 edges/thread.
__global__ void k_deg_acc(const int* __restrict__ ei,
                          const float* __restrict__ w) {
    int q = blockIdx.x * blockDim.x + threadIdx.x;   // quad index
    if (q >= NE / 4) return;
    int4   d4 = reinterpret_cast<const int4*>(ei + NE)[q];
    float4 w4 = reinterpret_cast<const float4*>(w)[q];
    atomicAdd(&g_deg[d4.x], w4.x);  atomicAdd(&g_cnt[d4.x], 1);
    atomicAdd(&g_deg[d4.y], w4.y);  atomicAdd(&g_cnt[d4.y], 1);
    atomicAdd(&g_deg[d4.z], w4.z);  atomicAdd(&g_cnt[d4.z], 1);
    atomicAdd(&g_deg[d4.w], w4.w);  atomicAdd(&g_cnt[d4.w], 1);
}

// scan phase A: per-chunk sums of g_cnt; also finalize deg_inv_sqrt
__global__ void k_scan_a() {
    __shared__ int red[256];
    int b = blockIdx.x, t = threadIdx.x;
    int base = b * CHUNK;
    int s = 0;
#pragma unroll
    for (int j = 0; j < CHUNK / 256; j++) {
        int i = base + j * 256 + t;
        if (i < NN) {
            s += g_cnt[i];
            g_deg[i] = rsqrtf(g_deg[i]);
        }
    }
    red[t] = s;
    __syncthreads();
    for (int off = 128; off > 0; off >>= 1) {
        if (t < off) red[t] += red[t + off];
        __syncthreads();
    }
    if (t == 0) g_bsum[b] = red[0];
}

// scan phase B: exclusive scan of NBLK chunk sums
__global__ void k_scan_b() {
    __shared__ int sh[128];
    int t = threadIdx.x;
    sh[t] = (t < NBLK) ? g_bsum[t] : 0;
    __syncthreads();
    for (int off = 1; off < 128; off <<= 1) {
        int v = (t >= off) ? sh[t - off] : 0;
        __syncthreads();
        sh[t] += v;
        __syncthreads();
    }
    if (t < NBLK) g_bpre[t] = (t == 0) ? 0 : sh[t - 1];
    if (t == NBLK - 1) g_rowstart[NN] = sh[t];
}

// scan phase C: local exclusive scan within chunk + chunk prefix
__global__ void k_scan_c() {
    __shared__ int sh[256];
    int b = blockIdx.x, t = threadIdx.x;
    int base = b * CHUNK;
    constexpr int PT = CHUNK / 256;
    int c[PT];
    int s = 0;
#pragma unroll
    for (int j = 0; j < PT; j++) {
        int i = base + t * PT + j;
        c[j] = (i < NN) ? g_cnt[i] : 0;
        s += c[j];
    }
    sh[t] = s;
    __syncthreads();
    for (int off = 1; off < 256; off <<= 1) {
        int v = (t >= off) ? sh[t - off] : 0;
        __syncthreads();
        sh[t] += v;
        __syncthreads();
    }
    int run = g_bpre[b] + ((t == 0) ? 0 : sh[t - 1]);
#pragma unroll
    for (int j = 0; j < PT; j++) {
        int i = base + t * PT + j;
        if (i < NN) g_rowstart[i] = run;
        run += c[j];
    }
}

// bucket edges by dst; one 8B (src,norm) record per edge. 4 edges/thread.
__global__ void k_bucket(const int* __restrict__ ei,
                         const float* __restrict__ w) {
    int q = blockIdx.x * blockDim.x + threadIdx.x;
    if (q >= NE / 4) return;
    int4   s4 = reinterpret_cast<const int4*>(ei)[q];
    int4   d4 = reinterpret_cast<const int4*>(ei + NE)[q];
    float4 w4 = reinterpret_cast<const float4*>(w)[q];
#pragma unroll
    for (int j = 0; j < 4; j++) {
        int   s = (j == 0) ? s4.x : (j == 1) ? s4.y : (j == 2) ? s4.z : s4.w;
        int   d = (j == 0) ? d4.x : (j == 1) ? d4.y : (j == 2) ? d4.z : d4.w;
        float v = (j == 0) ? w4.x : (j == 1) ? w4.y : (j == 2) ? w4.z : w4.w;
        int pos = g_rowstart[d] + atomicAdd(&g_cur[d], 1);
        Edge rec; rec.src = s; rec.nrm = g_deg[s] * v * g_deg[d];
        g_edge[pos] = rec;
    }
}

// ---------------- SGEMM: g_h = X @ W  (f32x2, dup-X smem: zero pack MOVs) ----
// BM=128 rows, BK=32, 256 threads, per-thread 8 rows x 8 cols
template <int DOUT, int XSEL>
__global__ void __launch_bounds__(256, 2) k_gemm(const float* __restrict__ Xext,
                                                 const float* __restrict__ W) {
    constexpr int BM = 128, BK = 32, TM = 8;
    constexpr int NCH = DOUT / 64;              // 2 for 128, 1 for 64
    constexpr int XS = BM + 2;                  // float2 row stride (even, 8B-aligned)
    __shared__ float2 Xs[BK][XS];               // duplicated (x,x) pairs
    __shared__ float  Ws[BK][DOUT];

    const float* X = (XSEL < 0) ? Xext : buf<(XSEL < 0) ? 0 : XSEL>();
    float* H = g_h;

    const int tid  = threadIdx.x;
    const int row0 = blockIdx.x * BM;
    const int tr   = tid >> 4;    // 0..15 (8 rows each)
    const int tc   = tid & 15;    // 0..15 (float4 col group per chunk)

    uint64_t acc[TM][NCH * 2];
#pragma unroll
    for (int a = 0; a < TM; a++)
#pragma unroll
        for (int c = 0; c < NCH * 2; c++) acc[a][c] = 0ull;

    for (int k0 = 0; k0 < DIN; k0 += BK) {
        // X tile: float4 global loads, duplicated float2 transpose stores
#pragma unroll
        for (int j = 0; j < 4; j++) {
            int i4 = tid + j * 256;      // 0..1023
            int m  = i4 >> 3;            // row in tile
            int k4 = i4 & 7;             // float4 index along k
            int r  = row0 + m;
            float4 v = make_float4(0.f, 0.f, 0.f, 0.f);
            if (r < NN)
                v = *reinterpret_cast<const float4*>(&X[(size_t)r * DIN + k0 + k4 * 4]);
            Xs[k4 * 4 + 0][m] = make_float2(v.x, v.x);
            Xs[k4 * 4 + 1][m] = make_float2(v.y, v.y);
            Xs[k4 * 4 + 2][m] = make_float2(v.z, v.z);
            Xs[k4 * 4 + 3][m] = make_float2(v.w, v.w);
        }
        // W tile: float4 loads + stores
#pragma unroll
        for (int i4 = tid; i4 < BK * DOUT / 4; i4 += 256) {
            int k  = i4 / (DOUT / 4);
            int c4 = i4 % (DOUT / 4);
            *reinterpret_cast<float4*>(&Ws[k][c4 * 4]) =
                *reinterpret_cast<const float4*>(&W[(size_t)(k0 + k) * DOUT + c4 * 4]);
        }
        __syncthreads();

#pragma unroll
        for (int k = 0; k < BK; k++) {
            uint64_t xv2[TM];
#pragma unroll
            for (int a = 0; a < TM; a++)
                xv2[a] = *reinterpret_cast<const uint64_t*>(&Xs[k][tr * TM + a]);
#pragma unroll
            for (int ch = 0; ch < NCH; ch++) {
                ulonglong2 w01 = *reinterpret_cast<const ulonglong2*>(
                    &Ws[k][ch * 64 + tc * 4]);
#pragma unroll
                for (int a = 0; a < TM; a++) {
                    ffma2(acc[a][ch * 2 + 0], xv2[a], w01.x);
                    ffma2(acc[a][ch * 2 + 1], xv2[a], w01.y);
                }
            }
        }
        __syncthreads();
    }

    // epilogue: float4 stores
#pragma unroll
    for (int a = 0; a < TM; a++) {
        int r = row0 + tr * TM + a;
        if (r >= NN) continue;
#pragma unroll
        for (int ch = 0; ch < NCH; ch++) {
            float4 o;
            unpack2(acc[a][ch * 2 + 0], o.x, o.y);
            unpack2(acc[a][ch * 2 + 1], o.z, o.w);
            *reinterpret_cast<float4*>(&H[(size_t)r * DOUT + ch * 64 + tc * 4]) = o;
        }
    }
}

// ------- fused aggregate: OUT[n] = sum_{CSR[n]} norm*g_h[src] + dinv^2*g_h[n] + bias, relu ----
// one warp per node; 8B edge records; 2-way unroll
template <int DOUT, bool RELU, int OSEL>
__global__ void k_agg(const float* __restrict__ bias,
                      float* __restrict__ OUText) {
    int warp = (blockIdx.x * blockDim.x + threadIdx.x) >> 5;
    int lane = threadIdx.x & 31;
    if (warp >= NN) return;

    float* OUT = (OSEL < 0) ? OUText : buf<(OSEL < 0) ? 0 : OSEL>();
    const float* H = g_h;

    int beg = g_rowstart[warp];
    int end = g_rowstart[warp + 1];
    float din = g_deg[warp];
    float sn  = din * din;

    if (DOUT == 128) {
        const float4* H4 = reinterpret_cast<const float4*>(H);
        float4 h = H4[(size_t)warp * 32 + lane];
        float4 acc = make_float4(h.x * sn, h.y * sn, h.z * sn, h.w * sn);
        int e = beg;
        for (; e + 1 < end; e += 2) {
            Edge e0 = g_edge[e], e1 = g_edge[e + 1];
            float4 v0 = H4[(size_t)e0.src * 32 + lane];
            float4 v1 = H4[(size_t)e1.src * 32 + lane];
            acc.x += e0.nrm * v0.x + e1.nrm * v1.x;
            acc.y += e0.nrm * v0.y + e1.nrm * v1.y;
            acc.z += e0.nrm * v0.z + e1.nrm * v1.z;
            acc.w += e0.nrm * v0.w + e1.nrm * v1.w;
        }
        if (e < end) {
            Edge e0 = g_edge[e];
            float4 v = H4[(size_t)e0.src * 32 + lane];
            acc.x += e0.nrm * v.x; acc.y += e0.nrm * v.y;
            acc.z += e0.nrm * v.z; acc.w += e0.nrm * v.w;
        }
        float4 bb = reinterpret_cast<const float4*>(bias)[lane];
        acc.x += bb.x; acc.y += bb.y; acc.z += bb.z; acc.w += bb.w;
        if (RELU) {
            acc.x = fmaxf(acc.x, 0.f); acc.y = fmaxf(acc.y, 0.f);
            acc.z = fmaxf(acc.z, 0.f); acc.w = fmaxf(acc.w, 0.f);
        }
        reinterpret_cast<float4*>(OUT)[(size_t)warp * 32 + lane] = acc;
    } else {
        const float2* H2 = reinterpret_cast<const float2*>(H);
        float2 h = H2[(size_t)warp * 32 + lane];
        float2 acc = make_float2(h.x * sn, h.y * sn);
        int e = beg;
        for (; e + 1 < end; e += 2) {
            Edge e0 = g_edge[e], e1 = g_edge[e + 1];
            float2 v0 = H2[(size_t)e0.src * 32 + lane];
            float2 v1 = H2[(size_t)e1.src * 32 + lane];
            acc.x += e0.nrm * v0.x + e1.nrm * v1.x;
            acc.y += e0.nrm * v0.y + e1.nrm * v1.y;
        }
        if (e < end) {
            Edge e0 = g_edge[e];
            float2 v = H2[(size_t)e0.src * 32 + lane];
            acc.x += e0.nrm * v.x; acc.y += e0.nrm * v.y;
        }
        float2 bb = reinterpret_cast<const float2*>(bias)[lane];
        acc.x += bb.x; acc.y += bb.y;
        if (RELU) { acc.x = fmaxf(acc.x, 0.f); acc.y = fmaxf(acc.y, 0.f); }
        reinterpret_cast<float2*>(OUT)[(size_t)warp * 32 + lane] = acc;
    }
}

// ---------------- driver (launches only) ----------------
extern "C" void kernel_launch(void* const* d_in, const int* in_sizes, int n_in,
                              void* d_out, int out_size) {
    const float* x  = (const float*)d_in[0];
    const int*   ei = (const int*)d_in[1];
    const float* ew = (const float*)d_in[2];
    const float* W0 = (const float*)d_in[3];
    const float* b0 = (const float*)d_in[4];
    const float* W1 = (const float*)d_in[5];
    const float* b1 = (const float*)d_in[6];
    const float* W2 = (const float*)d_in[7];
    const float* b2 = (const float*)d_in[8];
    float*       out = (float*)d_out;

    const int T = 256;
    k_init<<<(NN + T - 1) / T, T>>>();
    k_deg_acc<<<(NE / 4 + T - 1) / T, T>>>(ei, ew);
    k_scan_a<<<NBLK, 256>>>();
    k_scan_b<<<1, 128>>>();
    k_scan_c<<<NBLK, 256>>>();
    k_bucket<<<(NE / 4 + T - 1) / T, T>>>(ei, ew);

    const int gemm_blocks = (NN + 127) / 128;
    const int agg_blocks  = (NN * 32 + T - 1) / T;

    // layer 0: x -> g_a (d=128, relu)
    k_gemm<128, -1><<<gemm_blocks, 256>>>(x, W0);
    k_agg<128, true, 1><<<agg_blocks, T>>>(b0, nullptr);

    // layer 1: g_a -> g_b (d=128, relu)
    k_gemm<128, 1><<<gemm_blocks, 256>>>(nullptr, W1);
    k_agg<128, true, 2><<<agg_blocks, T>>>(b1, nullptr);

    // layer 2: g_b -> out (d=64, no relu)
    k_gemm<64, 2><<<gemm_blocks, 256>>>(nullptr, W2);
    k_agg<64, false, -1><<<agg_blocks, T>>>(b2, out);
}

// round 8
// speedup vs baseline: 1.1416x; 1.1416x over previous
#include <cuda_runtime.h>
#include <cstdint>

#define NN 100000
#define NE 1600000
#define DIN 128

#define CHUNK 1024
#define NBLK ((NN + CHUNK - 1) / CHUNK)   // 98 scan blocks

// ---------------- scratch (static __device__, no allocation) ----------------
__device__ __align__(16) float g_deg[NN];       // degree -> deg_inv_sqrt (in place)
__device__ int   g_cnt[NN];                     // in-degree counts (edges only)
__device__ int   g_cur[NN];                     // bucket cursors
__device__ int   g_rowstart[NN + 1];            // CSR row offsets (by dst)
__device__ int   g_bsum[NBLK];                  // per-chunk edge-count sums
__device__ int   g_bpre[NBLK];                  // exclusive prefix of chunk sums
struct __align__(8) Edge { int src; float nrm; };
__device__ Edge  g_edge[NE];                    // CSR-sorted (src, norm) records
__device__ __align__(16) float g_h[(size_t)NN * 128];   // transformed features
__device__ __align__(16) float g_a[(size_t)NN * 128];   // activation ping
__device__ __align__(16) float g_b[(size_t)NN * 128];   // activation pong

template <int SEL>
__device__ __forceinline__ float* buf() {
    if constexpr (SEL == 0) return g_h;
    else if constexpr (SEL == 1) return g_a;
    else return g_b;
}

// ---------------- packed f32x2 helpers ----------------
__device__ __forceinline__ uint64_t pack2(float lo, float hi) {
    uint64_t r;
    asm("mov.b64 %0, {%1, %2};" : "=l"(r) : "f"(lo), "f"(hi));
    return r;
}
__device__ __forceinline__ void ffma2(uint64_t& d, uint64_t a, uint64_t b) {
    asm("fma.rn.f32x2 %0, %1, %2, %0;" : "+l"(d) : "l"(a), "l"(b));
}
__device__ __forceinline__ void unpack2(uint64_t v, float& lo, float& hi) {
    asm("mov.b64 {%0, %1}, %2;" : "=f"(lo), "=f"(hi) : "l"(v));
}

// ---------------- preamble ----------------
__global__ void k_init() {
    int i = blockIdx.x * blockDim.x + threadIdx.x;
    if (i < NN) { g_deg[i] = 1.0f; g_cnt[i] = 0; g_cur[i] = 0; }
}

// edge_index delivered as int32: [0..NE) = src, [NE..2NE) = dst. 4 edges/thread.
__global__ void k_deg_acc(const int* __restrict__ ei,
                          const float* __restrict__ w) {
    int q = blockIdx.x * blockDim.x + threadIdx.x;
    if (q >= NE / 4) return;
    int4   d4 = reinterpret_cast<const int4*>(ei + NE)[q];
    float4 w4 = reinterpret_cast<const float4*>(w)[q];
    atomicAdd(&g_deg[d4.x], w4.x);  atomicAdd(&g_cnt[d4.x], 1);
    atomicAdd(&g_deg[d4.y], w4.y);  atomicAdd(&g_cnt[d4.y], 1);
    atomicAdd(&g_deg[d4.z], w4.z);  atomicAdd(&g_cnt[d4.z], 1);
    atomicAdd(&g_deg[d4.w], w4.w);  atomicAdd(&g_cnt[d4.w], 1);
}

// scan phase A: per-chunk sums of g_cnt; also finalize deg_inv_sqrt
__global__ void k_scan_a() {
    __shared__ int red[256];
    int b = blockIdx.x, t = threadIdx.x;
    int base = b * CHUNK;
    int s = 0;
#pragma unroll
    for (int j = 0; j < CHUNK / 256; j++) {
        int i = base + j * 256 + t;
        if (i < NN) {
            s += g_cnt[i];
            g_deg[i] = rsqrtf(g_deg[i]);
        }
    }
    red[t] = s;
    __syncthreads();
    for (int off = 128; off > 0; off >>= 1) {
        if (t < off) red[t] += red[t + off];
        __syncthreads();
    }
    if (t == 0) g_bsum[b] = red[0];
}

// scan phase B: exclusive scan of NBLK chunk sums
__global__ void k_scan_b() {
    __shared__ int sh[128];
    int t = threadIdx.x;
    sh[t] = (t < NBLK) ? g_bsum[t] : 0;
    __syncthreads();
    for (int off = 1; off < 128; off <<= 1) {
        int v = (t >= off) ? sh[t - off] : 0;
        __syncthreads();
        sh[t] += v;
        __syncthreads();
    }
    if (t < NBLK) g_bpre[t] = (t == 0) ? 0 : sh[t - 1];
    if (t == NBLK - 1) g_rowstart[NN] = sh[t];
}

// scan phase C: local exclusive scan within chunk + chunk prefix
__global__ void k_scan_c() {
    __shared__ int sh[256];
    int b = blockIdx.x, t = threadIdx.x;
    int base = b * CHUNK;
    constexpr int PT = CHUNK / 256;
    int c[PT];
    int s = 0;
#pragma unroll
    for (int j = 0; j < PT; j++) {
        int i = base + t * PT + j;
        c[j] = (i < NN) ? g_cnt[i] : 0;
        s += c[j];
    }
    sh[t] = s;
    __syncthreads();
    for (int off = 1; off < 256; off <<= 1) {
        int v = (t >= off) ? sh[t - off] : 0;
        __syncthreads();
        sh[t] += v;
        __syncthreads();
    }
    int run = g_bpre[b] + ((t == 0) ? 0 : sh[t - 1]);
#pragma unroll
    for (int j = 0; j < PT; j++) {
        int i = base + t * PT + j;
        if (i < NN) g_rowstart[i] = run;
        run += c[j];
    }
}

// bucket edges by dst; one 8B (src,norm) record per edge. 4 edges/thread.
__global__ void k_bucket(const int* __restrict__ ei,
                         const float* __restrict__ w) {
    int q = blockIdx.x * blockDim.x + threadIdx.x;
    if (q >= NE / 4) return;
    int4   s4 = reinterpret_cast<const int4*>(ei)[q];
    int4   d4 = reinterpret_cast<const int4*>(ei + NE)[q];
    float4 w4 = reinterpret_cast<const float4*>(w)[q];
#pragma unroll
    for (int j = 0; j < 4; j++) {
        int   s = (j == 0) ? s4.x : (j == 1) ? s4.y : (j == 2) ? s4.z : s4.w;
        int   d = (j == 0) ? d4.x : (j == 1) ? d4.y : (j == 2) ? d4.z : d4.w;
        float v = (j == 0) ? w4.x : (j == 1) ? w4.y : (j == 2) ? w4.z : w4.w;
        int pos = g_rowstart[d] + atomicAdd(&g_cur[d], 1);
        Edge rec; rec.src = s; rec.nrm = g_deg[s] * v * g_deg[d];
        g_edge[pos] = rec;
    }
}

// ---------------- SGEMM: g_h = X @ W  (R6 form: f32x2, scalar Xs, pad+1) ----
template <int DOUT, int XSEL>
__global__ void __launch_bounds__(256, 2) k_gemm(const float* __restrict__ Xext,
                                                 const float* __restrict__ W) {
    constexpr int BM = 128, BK = 32, TM = 8;
    constexpr int NCH = DOUT / 64;              // 2 for 128, 1 for 64
    __shared__ float Xs[BK][BM + 1];            // pad -> conflict-free transpose store
    __shared__ float Ws[BK][DOUT];

    const float* X = (XSEL < 0) ? Xext : buf<(XSEL < 0) ? 0 : XSEL>();
    float* H = g_h;

    const int tid  = threadIdx.x;
    const int row0 = blockIdx.x * BM;
    const int tr   = tid >> 4;    // 0..15 (8 rows each)
    const int tc   = tid & 15;    // 0..15 (float4 col group per chunk)

    uint64_t acc[TM][NCH * 2];
#pragma unroll
    for (int a = 0; a < TM; a++)
#pragma unroll
        for (int c = 0; c < NCH * 2; c++) acc[a][c] = 0ull;

    for (int k0 = 0; k0 < DIN; k0 += BK) {
#pragma unroll
        for (int j = 0; j < 4; j++) {
            int i4 = tid + j * 256;
            int m  = i4 >> 3;
            int k4 = i4 & 7;
            int r  = row0 + m;
            float4 v = make_float4(0.f, 0.f, 0.f, 0.f);
            if (r < NN)
                v = *reinterpret_cast<const float4*>(&X[(size_t)r * DIN + k0 + k4 * 4]);
            Xs[k4 * 4 + 0][m] = v.x;
            Xs[k4 * 4 + 1][m] = v.y;
            Xs[k4 * 4 + 2][m] = v.z;
            Xs[k4 * 4 + 3][m] = v.w;
        }
#pragma unroll
        for (int i4 = tid; i4 < BK * DOUT / 4; i4 += 256) {
            int k  = i4 / (DOUT / 4);
            int c4 = i4 % (DOUT / 4);
            *reinterpret_cast<float4*>(&Ws[k][c4 * 4]) =
                *reinterpret_cast<const float4*>(&W[(size_t)(k0 + k) * DOUT + c4 * 4]);
        }
        __syncthreads();

#pragma unroll
        for (int k = 0; k < BK; k++) {
            uint64_t xv2[TM];
#pragma unroll
            for (int a = 0; a < TM; a++) {
                float xv = Xs[k][tr * TM + a];
                xv2[a] = pack2(xv, xv);
            }
#pragma unroll
            for (int ch = 0; ch < NCH; ch++) {
                ulonglong2 w01 = *reinterpret_cast<const ulonglong2*>(
                    &Ws[k][ch * 64 + tc * 4]);
#pragma unroll
                for (int a = 0; a < TM; a++) {
                    ffma2(acc[a][ch * 2 + 0], xv2[a], w01.x);
                    ffma2(acc[a][ch * 2 + 1], xv2[a], w01.y);
                }
            }
        }
        __syncthreads();
    }

#pragma unroll
    for (int a = 0; a < TM; a++) {
        int r = row0 + tr * TM + a;
        if (r >= NN) continue;
#pragma unroll
        for (int ch = 0; ch < NCH; ch++) {
            float4 o;
            unpack2(acc[a][ch * 2 + 0], o.x, o.y);
            unpack2(acc[a][ch * 2 + 1], o.z, o.w);
            *reinterpret_cast<float4*>(&H[(size_t)r * DOUT + ch * 64 + tc * 4]) = o;
        }
    }
}

// ------- fused aggregate: OUT[n] = sum_{CSR[n]} norm*g_h[src] + dinv^2*g_h[n] + bias, relu ----
template <int DOUT, bool RELU, int OSEL>
__global__ void k_agg(const float* __restrict__ bias,
                      float* __restrict__ OUText) {
    int warp = (blockIdx.x * blockDim.x + threadIdx.x) >> 5;
    int lane = threadIdx.x & 31;
    if (warp >= NN) return;

    float* OUT = (OSEL < 0) ? OUText : buf<(OSEL < 0) ? 0 : OSEL>();
    const float* H = g_h;

    int beg = g_rowstart[warp];
    int end = g_rowstart[warp + 1];
    float din = g_deg[warp];
    float sn  = din * din;

    if (DOUT == 128) {
        const float4* H4 = reinterpret_cast<const float4*>(H);
        float4 h = H4[(size_t)warp * 32 + lane];
        float4 acc = make_float4(h.x * sn, h.y * sn, h.z * sn, h.w * sn);
        int e = beg;
        for (; e + 1 < end; e += 2) {
            Edge e0 = g_edge[e], e1 = g_edge[e + 1];
            float4 v0 = H4[(size_t)e0.src * 32 + lane];
            float4 v1 = H4[(size_t)e1.src * 32 + lane];
            acc.x += e0.nrm * v0.x + e1.nrm * v1.x;
            acc.y += e0.nrm * v0.y + e1.nrm * v1.y;
            acc.z += e0.nrm * v0.z + e1.nrm * v1.z;
            acc.w += e0.nrm * v0.w + e1.nrm * v1.w;
        }
        if (e < end) {
            Edge e0 = g_edge[e];
            float4 v = H4[(size_t)e0.src * 32 + lane];
            acc.x += e0.nrm * v.x; acc.y += e0.nrm * v.y;
            acc.z += e0.nrm * v.z; acc.w += e0.nrm * v.w;
        }
        float4 bb = reinterpret_cast<const float4*>(bias)[lane];
        acc.x += bb.x; acc.y += bb.y; acc.z += bb.z; acc.w += bb.w;
        if (RELU) {
            acc.x = fmaxf(acc.x, 0.f); acc.y = fmaxf(acc.y, 0.f);
            acc.z = fmaxf(acc.z, 0.f); acc.w = fmaxf(acc.w, 0.f);
        }
        reinterpret_cast<float4*>(OUT)[(size_t)warp * 32 + lane] = acc;
    } else {
        const float2* H2 = reinterpret_cast<const float2*>(H);
        float2 h = H2[(size_t)warp * 32 + lane];
        float2 acc = make_float2(h.x * sn, h.y * sn);
        int e = beg;
        for (; e + 1 < end; e += 2) {
            Edge e0 = g_edge[e], e1 = g_edge[e + 1];
            float2 v0 = H2[(size_t)e0.src * 32 + lane];
            float2 v1 = H2[(size_t)e1.src * 32 + lane];
            acc.x += e0.nrm * v0.x + e1.nrm * v1.x;
            acc.y += e0.nrm * v0.y + e1.nrm * v1.y;
        }
        if (e < end) {
            Edge e0 = g_edge[e];
            float2 v = H2[(size_t)e0.src * 32 + lane];
            acc.x += e0.nrm * v.x; acc.y += e0.nrm * v.y;
        }
        float2 bb = reinterpret_cast<const float2*>(bias)[lane];
        acc.x += bb.x; acc.y += bb.y;
        if (RELU) { acc.x = fmaxf(acc.x, 0.f); acc.y = fmaxf(acc.y, 0.f); }
        reinterpret_cast<float2*>(OUT)[(size_t)warp * 32 + lane] = acc;
    }
}

// ---------------- driver: fork preamble onto side stream, join before agg0 ----
extern "C" void kernel_launch(void* const* d_in, const int* in_sizes, int n_in,
                              void* d_out, int out_size) {
    const float* x  = (const float*)d_in[0];
    const int*   ei = (const int*)d_in[1];
    const float* ew = (const float*)d_in[2];
    const float* W0 = (const float*)d_in[3];
    const float* b0 = (const float*)d_in[4];
    const float* W1 = (const float*)d_in[5];
    const float* b1 = (const float*)d_in[6];
    const float* W2 = (const float*)d_in[7];
    const float* b2 = (const float*)d_in[8];
    float*       out = (float*)d_out;

    static cudaStream_t s2 = nullptr;
    static cudaEvent_t  ev_fork = nullptr, ev_join = nullptr;
    static bool tried = false;
    if (!tried) {
        tried = true;
        if (cudaStreamCreateWithFlags(&s2, cudaStreamNonBlocking) != cudaSuccess) s2 = nullptr;
        if (cudaEventCreateWithFlags(&ev_fork, cudaEventDisableTiming) != cudaSuccess) ev_fork = nullptr;
        if (cudaEventCreateWithFlags(&ev_join, cudaEventDisableTiming) != cudaSuccess) ev_join = nullptr;
    }
    const bool fork = (s2 && ev_fork && ev_join);
    cudaStream_t sp = fork ? s2 : (cudaStream_t)0;   // preamble stream

    const int T = 256;
    if (fork) {
        cudaEventRecord(ev_fork, 0);
        cudaStreamWaitEvent(s2, ev_fork, 0);
    }
    // preamble on sp (independent of GEMM0)
    k_init<<<(NN + T - 1) / T, T, 0, sp>>>();
    k_deg_acc<<<(NE / 4 + T - 1) / T, T, 0, sp>>>(ei, ew);
    k_scan_a<<<NBLK, 256, 0, sp>>>();
    k_scan_b<<<1, 128, 0, sp>>>();
    k_scan_c<<<NBLK, 256, 0, sp>>>();
    k_bucket<<<(NE / 4 + T - 1) / T, T, 0, sp>>>(ei, ew);
    if (fork) cudaEventRecord(ev_join, s2);

    const int gemm_blocks = (NN + 127) / 128;
    const int agg_blocks  = (NN * 32 + T - 1) / T;

    // layer 0 GEMM overlaps the preamble
    k_gemm<128, -1><<<gemm_blocks, 256>>>(x, W0);
    if (fork) cudaStreamWaitEvent(0, ev_join, 0);
    k_agg<128, true, 1><<<agg_blocks, T>>>(b0, nullptr);

    // layer 1: g_a -> g_b (d=128, relu)
    k_gemm<128, 1><<<gemm_blocks, 256>>>(nullptr, W1);
    k_agg<128, true, 2><<<agg_blocks, T>>>(b1, nullptr);

    // layer 2: g_b -> out (d=64, no relu)
    k_gemm<64, 2><<<gemm_blocks, 256>>>(nullptr, W2);
    k_agg<64, false, -1><<<agg_blocks, T>>>(b2, out);
}

// round 9
// speedup vs baseline: 1.2221x; 1.0705x over previous
#include <cuda_runtime.h>
#include <cuda_fp16.h>
#include <cstdint>

#define NN 100000
#define NE 1600000
#define DIN 128

#define CHUNK 1024
#define NBLK ((NN + CHUNK - 1) / CHUNK)   // 98 scan blocks

// ---------------- scratch (static __device__, no allocation) ----------------
__device__ __align__(16) float g_deg[NN];       // degree -> deg_inv_sqrt (in place)
__device__ int   g_cnt[NN];                     // in-degree counts (edges only)
__device__ int   g_cur[NN];                     // bucket cursors
__device__ int   g_rowstart[NN + 1];            // CSR row offsets (by dst)
__device__ int   g_bsum[NBLK];                  // per-chunk edge-count sums
__device__ int   g_bpre[NBLK];                  // exclusive prefix of chunk sums
struct __align__(8) Edge { int src; float nrm; };
__device__ Edge  g_edge[NE];                    // CSR-sorted (src, norm) records
__device__ __align__(16) __half g_hh[(size_t)NN * 128];  // fp16 transformed features
__device__ __align__(16) float  g_a[(size_t)NN * 128];   // activation ping
__device__ __align__(16) float  g_b[(size_t)NN * 128];   // activation pong

template <int SEL>
__device__ __forceinline__ float* buf() {
    if constexpr (SEL == 1) return g_a;
    else return g_b;
}

// ---------------- packed f32x2 helpers ----------------
__device__ __forceinline__ uint64_t pack2(float lo, float hi) {
    uint64_t r;
    asm("mov.b64 %0, {%1, %2};" : "=l"(r) : "f"(lo), "f"(hi));
    return r;
}
__device__ __forceinline__ void ffma2(uint64_t& d, uint64_t a, uint64_t b) {
    asm("fma.rn.f32x2 %0, %1, %2, %0;" : "+l"(d) : "l"(a), "l"(b));
}
__device__ __forceinline__ void unpack2(uint64_t v, float& lo, float& hi) {
    asm("mov.b64 {%0, %1}, %2;" : "=f"(lo), "=f"(hi) : "l"(v));
}

// ---------------- preamble ----------------
__global__ void k_init() {
    int i = blockIdx.x * blockDim.x + threadIdx.x;
    if (i < NN) { g_deg[i] = 1.0f; g_cnt[i] = 0; g_cur[i] = 0; }
}

__global__ void k_deg_acc(const int* __restrict__ ei,
                          const float* __restrict__ w) {
    int q = blockIdx.x * blockDim.x + threadIdx.x;
    if (q >= NE / 4) return;
    int4   d4 = reinterpret_cast<const int4*>(ei + NE)[q];
    float4 w4 = reinterpret_cast<const float4*>(w)[q];
    atomicAdd(&g_deg[d4.x], w4.x);  atomicAdd(&g_cnt[d4.x], 1);
    atomicAdd(&g_deg[d4.y], w4.y);  atomicAdd(&g_cnt[d4.y], 1);
    atomicAdd(&g_deg[d4.z], w4.z);  atomicAdd(&g_cnt[d4.z], 1);
    atomicAdd(&g_deg[d4.w], w4.w);  atomicAdd(&g_cnt[d4.w], 1);
}

__global__ void k_scan_a() {
    __shared__ int red[256];
    int b = blockIdx.x, t = threadIdx.x;
    int base = b * CHUNK;
    int s = 0;
#pragma unroll
    for (int j = 0; j < CHUNK / 256; j++) {
        int i = base + j * 256 + t;
        if (i < NN) {
            s += g_cnt[i];
            g_deg[i] = rsqrtf(g_deg[i]);
        }
    }
    red[t] = s;
    __syncthreads();
    for (int off = 128; off > 0; off >>= 1) {
        if (t < off) red[t] += red[t + off];
        __syncthreads();
    }
    if (t == 0) g_bsum[b] = red[0];
}

__global__ void k_scan_b() {
    __shared__ int sh[128];
    int t = threadIdx.x;
    sh[t] = (t < NBLK) ? g_bsum[t] : 0;
    __syncthreads();
    for (int off = 1; off < 128; off <<= 1) {
        int v = (t >= off) ? sh[t - off] : 0;
        __syncthreads();
        sh[t] += v;
        __syncthreads();
    }
    if (t < NBLK) g_bpre[t] = (t == 0) ? 0 : sh[t - 1];
    if (t == NBLK - 1) g_rowstart[NN] = sh[t];
}

__global__ void k_scan_c() {
    __shared__ int sh[256];
    int b = blockIdx.x, t = threadIdx.x;
    int base = b * CHUNK;
    constexpr int PT = CHUNK / 256;
    int c[PT];
    int s = 0;
#pragma unroll
    for (int j = 0; j < PT; j++) {
        int i = base + t * PT + j;
        c[j] = (i < NN) ? g_cnt[i] : 0;
        s += c[j];
    }
    sh[t] = s;
    __syncthreads();
    for (int off = 1; off < 256; off <<= 1) {
        int v = (t >= off) ? sh[t - off] : 0;
        __syncthreads();
        sh[t] += v;
        __syncthreads();
    }
    int run = g_bpre[b] + ((t == 0) ? 0 : sh[t - 1]);
#pragma unroll
    for (int j = 0; j < PT; j++) {
        int i = base + t * PT + j;
        if (i < NN) g_rowstart[i] = run;
        run += c[j];
    }
}

__global__ void k_bucket(const int* __restrict__ ei,
                         const float* __restrict__ w) {
    int q = blockIdx.x * blockDim.x + threadIdx.x;
    if (q >= NE / 4) return;
    int4   s4 = reinterpret_cast<const int4*>(ei)[q];
    int4   d4 = reinterpret_cast<const int4*>(ei + NE)[q];
    float4 w4 = reinterpret_cast<const float4*>(w)[q];
#pragma unroll
    for (int j = 0; j < 4; j++) {
        int   s = (j == 0) ? s4.x : (j == 1) ? s4.y : (j == 2) ? s4.z : s4.w;
        int   d = (j == 0) ? d4.x : (j == 1) ? d4.y : (j == 2) ? d4.z : d4.w;
        float v = (j == 0) ? w4.x : (j == 1) ? w4.y : (j == 2) ? w4.z : w4.w;
        int pos = g_rowstart[d] + atomicAdd(&g_cur[d], 1);
        Edge rec; rec.src = s; rec.nrm = g_deg[s] * v * g_deg[d];
        g_edge[pos] = rec;
    }
}

// ---------------- SGEMM: g_hh = fp16(X @ W)  (f32x2 core, fp16 epilogue) ----
template <int DOUT, int XSEL>
__global__ void __launch_bounds__(256, 2) k_gemm(const float* __restrict__ Xext,
                                                 const float* __restrict__ W) {
    constexpr int BM = 128, BK = 32, TM = 8;
    constexpr int NCH = DOUT / 64;              // 2 for 128, 1 for 64
    __shared__ float Xs[BK][BM + 1];            // pad -> conflict-free transpose store
    __shared__ float Ws[BK][DOUT];

    const float* X = (XSEL < 0) ? Xext : buf<(XSEL < 0) ? 1 : XSEL>();

    const int tid  = threadIdx.x;
    const int row0 = blockIdx.x * BM;
    const int tr   = tid >> 4;
    const int tc   = tid & 15;

    uint64_t acc[TM][NCH * 2];
#pragma unroll
    for (int a = 0; a < TM; a++)
#pragma unroll
        for (int c = 0; c < NCH * 2; c++) acc[a][c] = 0ull;

    for (int k0 = 0; k0 < DIN; k0 += BK) {
#pragma unroll
        for (int j = 0; j < 4; j++) {
            int i4 = tid + j * 256;
            int m  = i4 >> 3;
            int k4 = i4 & 7;
            int r  = row0 + m;
            float4 v = make_float4(0.f, 0.f, 0.f, 0.f);
            if (r < NN)
                v = *reinterpret_cast<const float4*>(&X[(size_t)r * DIN + k0 + k4 * 4]);
            Xs[k4 * 4 + 0][m] = v.x;
            Xs[k4 * 4 + 1][m] = v.y;
            Xs[k4 * 4 + 2][m] = v.z;
            Xs[k4 * 4 + 3][m] = v.w;
        }
#pragma unroll
        for (int i4 = tid; i4 < BK * DOUT / 4; i4 += 256) {
            int k  = i4 / (DOUT / 4);
            int c4 = i4 % (DOUT / 4);
            *reinterpret_cast<float4*>(&Ws[k][c4 * 4]) =
                *reinterpret_cast<const float4*>(&W[(size_t)(k0 + k) * DOUT + c4 * 4]);
        }
        __syncthreads();

#pragma unroll
        for (int k = 0; k < BK; k++) {
            uint64_t xv2[TM];
#pragma unroll
            for (int a = 0; a < TM; a++) {
                float xv = Xs[k][tr * TM + a];
                xv2[a] = pack2(xv, xv);
            }
#pragma unroll
            for (int ch = 0; ch < NCH; ch++) {
                ulonglong2 w01 = *reinterpret_cast<const ulonglong2*>(
                    &Ws[k][ch * 64 + tc * 4]);
#pragma unroll
                for (int a = 0; a < TM; a++) {
                    ffma2(acc[a][ch * 2 + 0], xv2[a], w01.x);
                    ffma2(acc[a][ch * 2 + 1], xv2[a], w01.y);
                }
            }
        }
        __syncthreads();
    }

    // epilogue: fp16 convert + 8B stores
#pragma unroll
    for (int a = 0; a < TM; a++) {
        int r = row0 + tr * TM + a;
        if (r >= NN) continue;
#pragma unroll
        for (int ch = 0; ch < NCH; ch++) {
            float4 o;
            unpack2(acc[a][ch * 2 + 0], o.x, o.y);
            unpack2(acc[a][ch * 2 + 1], o.z, o.w);
            __half2 h01 = __floats2half2_rn(o.x, o.y);
            __half2 h23 = __floats2half2_rn(o.z, o.w);
            uint2 pk;
            *reinterpret_cast<__half2*>(&pk.x) = h01;
            *reinterpret_cast<__half2*>(&pk.y) = h23;
            *reinterpret_cast<uint2*>(&g_hh[(size_t)r * DOUT + ch * 64 + tc * 4]) = pk;
        }
    }
}

// ------- fused aggregate over fp16 H, fp32 accumulate -------
// d=128: 4 halfs (8B) per lane; d=64: 2 halfs (4B) per lane
template <int DOUT, bool RELU, int OSEL>
__global__ void k_agg(const float* __restrict__ bias,
                      float* __restrict__ OUText) {
    int warp = (blockIdx.x * blockDim.x + threadIdx.x) >> 5;
    int lane = threadIdx.x & 31;
    if (warp >= NN) return;

    float* OUT = (OSEL < 0) ? OUText : buf<(OSEL < 0) ? 1 : OSEL>();

    int beg = g_rowstart[warp];
    int end = g_rowstart[warp + 1];
    float din = g_deg[warp];
    float sn  = din * din;

    if (DOUT == 128) {
        const uint2* HH = reinterpret_cast<const uint2*>(g_hh);
        uint2 hr = HH[(size_t)warp * 32 + lane];
        float2 h01 = __half22float2(*reinterpret_cast<__half2*>(&hr.x));
        float2 h23 = __half22float2(*reinterpret_cast<__half2*>(&hr.y));
        float4 acc = make_float4(h01.x * sn, h01.y * sn, h23.x * sn, h23.y * sn);
        int e = beg;
        for (; e + 1 < end; e += 2) {
            Edge e0 = g_edge[e], e1 = g_edge[e + 1];
            uint2 r0 = HH[(size_t)e0.src * 32 + lane];
            uint2 r1 = HH[(size_t)e1.src * 32 + lane];
            float2 a01 = __half22float2(*reinterpret_cast<__half2*>(&r0.x));
            float2 a23 = __half22float2(*reinterpret_cast<__half2*>(&r0.y));
            float2 b01 = __half22float2(*reinterpret_cast<__half2*>(&r1.x));
            float2 b23 = __half22float2(*reinterpret_cast<__half2*>(&r1.y));
            acc.x += e0.nrm * a01.x + e1.nrm * b01.x;
            acc.y += e0.nrm * a01.y + e1.nrm * b01.y;
            acc.z += e0.nrm * a23.x + e1.nrm * b23.x;
            acc.w += e0.nrm * a23.y + e1.nrm * b23.y;
        }
        if (e < end) {
            Edge e0 = g_edge[e];
            uint2 r0 = HH[(size_t)e0.src * 32 + lane];
            float2 a01 = __half22float2(*reinterpret_cast<__half2*>(&r0.x));
            float2 a23 = __half22float2(*reinterpret_cast<__half2*>(&r0.y));
            acc.x += e0.nrm * a01.x; acc.y += e0.nrm * a01.y;
            acc.z += e0.nrm * a23.x; acc.w += e0.nrm * a23.y;
        }
        float4 bb = reinterpret_cast<const float4*>(bias)[lane];
        acc.x += bb.x; acc.y += bb.y; acc.z += bb.z; acc.w += bb.w;
        if (RELU) {
            acc.x = fmaxf(acc.x, 0.f); acc.y = fmaxf(acc.y, 0.f);
            acc.z = fmaxf(acc.z, 0.f); acc.w = fmaxf(acc.w, 0.f);
        }
        reinterpret_cast<float4*>(OUT)[(size_t)warp * 32 + lane] = acc;
    } else {
        const __half2* HH = reinterpret_cast<const __half2*>(g_hh);
        float2 h = __half22float2(HH[(size_t)warp * 32 + lane]);
        float2 acc = make_float2(h.x * sn, h.y * sn);
        int e = beg;
        for (; e + 1 < end; e += 2) {
            Edge e0 = g_edge[e], e1 = g_edge[e + 1];
            float2 v0 = __half22float2(HH[(size_t)e0.src * 32 + lane]);
            float2 v1 = __half22float2(HH[(size_t)e1.src * 32 + lane]);
            acc.x += e0.nrm * v0.x + e1.nrm * v1.x;
            acc.y += e0.nrm * v0.y + e1.nrm * v1.y;
        }
        if (e < end) {
            Edge e0 = g_edge[e];
            float2 v = __half22float2(HH[(size_t)e0.src * 32 + lane]);
            acc.x += e0.nrm * v.x; acc.y += e0.nrm * v.y;
        }
        float2 bb = reinterpret_cast<const float2*>(bias)[lane];
        acc.x += bb.x; acc.y += bb.y;
        if (RELU) { acc.x = fmaxf(acc.x, 0.f); acc.y = fmaxf(acc.y, 0.f); }
        reinterpret_cast<float2*>(OUT)[(size_t)warp * 32 + lane] = acc;
    }
}

// ---------------- driver: fork preamble onto side stream, join before agg0 ----
extern "C" void kernel_launch(void* const* d_in, const int* in_sizes, int n_in,
                              void* d_out, int out_size) {
    const float* x  = (const float*)d_in[0];
    const int*   ei = (const int*)d_in[1];
    const float* ew = (const float*)d_in[2];
    const float* W0 = (const float*)d_in[3];
    const float* b0 = (const float*)d_in[4];
    const float* W1 = (const float*)d_in[5];
    const float* b1 = (const float*)d_in[6];
    const float* W2 = (const float*)d_in[7];
    const float* b2 = (const float*)d_in[8];
    float*       out = (float*)d_out;

    static cudaStream_t s2 = nullptr;
    static cudaEvent_t  ev_fork = nullptr, ev_join = nullptr;
    static bool tried = false;
    if (!tried) {
        tried = true;
        if (cudaStreamCreateWithFlags(&s2, cudaStreamNonBlocking) != cudaSuccess) s2 = nullptr;
        if (cudaEventCreateWithFlags(&ev_fork, cudaEventDisableTiming) != cudaSuccess) ev_fork = nullptr;
        if (cudaEventCreateWithFlags(&ev_join, cudaEventDisableTiming) != cudaSuccess) ev_join = nullptr;
    }
    const bool fork = (s2 && ev_fork && ev_join);
    cudaStream_t sp = fork ? s2 : (cudaStream_t)0;

    const int T = 256;
    if (fork) {
        cudaEventRecord(ev_fork, 0);
        cudaStreamWaitEvent(s2, ev_fork, 0);
    }
    k_init<<<(NN + T - 1) / T, T, 0, sp>>>();
    k_deg_acc<<<(NE / 4 + T - 1) / T, T, 0, sp>>>(ei, ew);
    k_scan_a<<<NBLK, 256, 0, sp>>>();
    k_scan_b<<<1, 128, 0, sp>>>();
    k_scan_c<<<NBLK, 256, 0, sp>>>();
    k_bucket<<<(NE / 4 + T - 1) / T, T, 0, sp>>>(ei, ew);
    if (fork) cudaEventRecord(ev_join, s2);

    const int gemm_blocks = (NN + 127) / 128;
    const int agg_blocks  = (NN * 32 + T - 1) / T;

    // layer 0 GEMM overlaps the preamble
    k_gemm<128, -1><<<gemm_blocks, 256>>>(x, W0);
    if (fork) cudaStreamWaitEvent(0, ev_join, 0);
    k_agg<128, true, 1><<<agg_blocks, T>>>(b0, nullptr);

    // layer 1
    k_gemm<128, 1><<<gemm_blocks, 256>>>(nullptr, W1);
    k_agg<128, true, 2><<<agg_blocks, T>>>(b1, nullptr);

    // layer 2
    k_gemm<64, 2><<<gemm_blocks, 256>>>(nullptr, W2);
    k_agg<64, false, -1><<<agg_blocks, T>>>(b2, out);
}

// round 11
// speedup vs baseline: 1.6856x; 1.3793x over previous
#include <cuda_runtime.h>
#include <cuda_fp16.h>
#include <cstdint>

#define NN 100000
#define NE 1600000
#define DIN 128

#define CHUNK 1024
#define NBLK ((NN + CHUNK - 1) / CHUNK)   // 98 scan blocks

// ---------------- scratch (static __device__, no allocation) ----------------
__device__ __align__(16) float g_deg[NN];
__device__ int   g_cnt[NN];
__device__ int   g_cur[NN];
__device__ int   g_rowstart[NN + 1];
__device__ int   g_bsum[NBLK];
__device__ int   g_bpre[NBLK];
struct __align__(8) Edge { int src; float nrm; };
__device__ Edge  g_edge[NE];
__device__ __align__(16) __half g_hh[(size_t)NN * 128];   // H = X@W (fp16)
__device__ __align__(16) __half g_ah[(size_t)NN * 128];   // activation ping (fp16)
__device__ __align__(16) __half g_bh[(size_t)NN * 128];   // activation pong (fp16)
__device__ __align__(16) __half g_wt0[128 * 128];         // W0^T fp16 [n][k]
__device__ __align__(16) __half g_wt1[128 * 128];         // W1^T
__device__ __align__(16) __half g_wt2[64 * 128];          // W2^T

template <int SEL>
__device__ __forceinline__ const __half* bufh() {
    if constexpr (SEL == 1) return g_ah;
    else return g_bh;
}

// ---------------- HMMA helpers (sm_80+ ISA, valid on plain sm_103) ----------
__device__ __forceinline__ uint32_t smem_u32(const void* p) {
    uint32_t a;
    asm("{ .reg .u64 t; cvta.to.shared.u64 t, %1; cvt.u32.u64 %0, t; }" : "=r"(a) : "l"(p));
    return a;
}
__device__ __forceinline__ void ldsm_x4(uint32_t* r, uint32_t addr) {
    asm volatile("ldmatrix.sync.aligned.m8n8.x4.shared.b16 {%0,%1,%2,%3}, [%4];"
                 : "=r"(r[0]), "=r"(r[1]), "=r"(r[2]), "=r"(r[3]) : "r"(addr));
}
__device__ __forceinline__ void ldsm_x2(uint32_t* r, uint32_t addr) {
    asm volatile("ldmatrix.sync.aligned.m8n8.x2.shared.b16 {%0,%1}, [%2];"
                 : "=r"(r[0]), "=r"(r[1]) : "r"(addr));
}
__device__ __forceinline__ void mma16816(float* c, const uint32_t* a, const uint32_t* b) {
    asm volatile("mma.sync.aligned.m16n8k16.row.col.f32.f16.f16.f32 "
                 "{%0,%1,%2,%3}, {%4,%5,%6,%7}, {%8,%9}, {%0,%1,%2,%3};"
                 : "+f"(c[0]), "+f"(c[1]), "+f"(c[2]), "+f"(c[3])
                 : "r"(a[0]), "r"(a[1]), "r"(a[2]), "r"(a[3]), "r"(b[0]), "r"(b[1]));
}

// ---------------- preamble ----------------
__global__ void k_init() {
    int i = blockIdx.x * blockDim.x + threadIdx.x;
    if (i < NN) { g_deg[i] = 1.0f; g_cnt[i] = 0; g_cur[i] = 0; }
}

__global__ void k_deg_acc(const int* __restrict__ ei, const float* __restrict__ w) {
    int q = blockIdx.x * blockDim.x + threadIdx.x;
    if (q >= NE / 4) return;
    int4   d4 = reinterpret_cast<const int4*>(ei + NE)[q];
    float4 w4 = reinterpret_cast<const float4*>(w)[q];
    atomicAdd(&g_deg[d4.x], w4.x);  atomicAdd(&g_cnt[d4.x], 1);
    atomicAdd(&g_deg[d4.y], w4.y);  atomicAdd(&g_cnt[d4.y], 1);
    atomicAdd(&g_deg[d4.z], w4.z);  atomicAdd(&g_cnt[d4.z], 1);
    atomicAdd(&g_deg[d4.w], w4.w);  atomicAdd(&g_cnt[d4.w], 1);
}

__global__ void k_scan_a() {
    __shared__ int red[256];
    int b = blockIdx.x, t = threadIdx.x;
    int base = b * CHUNK;
    int s = 0;
#pragma unroll
    for (int j = 0; j < CHUNK / 256; j++) {
        int i = base + j * 256 + t;
        if (i < NN) { s += g_cnt[i]; g_deg[i] = rsqrtf(g_deg[i]); }
    }
    red[t] = s;
    __syncthreads();
    for (int off = 128; off > 0; off >>= 1) {
        if (t < off) red[t] += red[t + off];
        __syncthreads();
    }
    if (t == 0) g_bsum[b] = red[0];
}

__global__ void k_scan_b() {
    __shared__ int sh[128];
    int t = threadIdx.x;
    sh[t] = (t < NBLK) ? g_bsum[t] : 0;
    __syncthreads();
    for (int off = 1; off < 128; off <<= 1) {
        int v = (t >= off) ? sh[t - off] : 0;
        __syncthreads();
        sh[t] += v;
        __syncthreads();
    }
    if (t < NBLK) g_bpre[t] = (t == 0) ? 0 : sh[t - 1];
    if (t == NBLK - 1) g_rowstart[NN] = sh[t];
}

__global__ void k_scan_c() {
    __shared__ int sh[256];
    int b = blockIdx.x, t = threadIdx.x;
    int base = b * CHUNK;
    constexpr int PT = CHUNK / 256;
    int c[PT];
    int s = 0;
#pragma unroll
    for (int j = 0; j < PT; j++) {
        int i = base + t * PT + j;
        c[j] = (i < NN) ? g_cnt[i] : 0;
        s += c[j];
    }
    sh[t] = s;
    __syncthreads();
    for (int off = 1; off < 256; off <<= 1) {
        int v = (t >= off) ? sh[t - off] : 0;
        __syncthreads();
        sh[t] += v;
        __syncthreads();
    }
    int run = g_bpre[b] + ((t == 0) ? 0 : sh[t - 1]);
#pragma unroll
    for (int j = 0; j < PT; j++) {
        int i = base + t * PT + j;
        if (i < NN) g_rowstart[i] = run;
        run += c[j];
    }
}

__global__ void k_bucket(const int* __restrict__ ei, const float* __restrict__ w) {
    int q = blockIdx.x * blockDim.x + threadIdx.x;
    if (q >= NE / 4) return;
    int4   s4 = reinterpret_cast<const int4*>(ei)[q];
    int4   d4 = reinterpret_cast<const int4*>(ei + NE)[q];
    float4 w4 = reinterpret_cast<const float4*>(w)[q];
#pragma unroll
    for (int j = 0; j < 4; j++) {
        int   s = (j == 0) ? s4.x : (j == 1) ? s4.y : (j == 2) ? s4.z : s4.w;
        int   d = (j == 0) ? d4.x : (j == 1) ? d4.y : (j == 2) ? d4.z : d4.w;
        float v = (j == 0) ? w4.x : (j == 1) ? w4.y : (j == 2) ? w4.z : w4.w;
        int pos = g_rowstart[d] + atomicAdd(&g_cur[d], 1);
        Edge rec; rec.src = s; rec.nrm = g_deg[s] * v * g_deg[d];
        g_edge[pos] = rec;
    }
}

// weights -> transposed fp16 [n][k]
__global__ void k_wconv(const float* __restrict__ W0, const float* __restrict__ W1,
                        const float* __restrict__ W2) {
    int i = blockIdx.x * blockDim.x + threadIdx.x;
    if (i < 128 * 128) {
        int k = i >> 7, n = i & 127;
        g_wt0[n * 128 + k] = __float2half(W0[i]);
        g_wt1[n * 128 + k] = __float2half(W1[i]);
    }
    if (i < 128 * 64) {
        int k = i / 64, n = i % 64;
        g_wt2[n * 128 + k] = __float2half(W2[i]);
    }
}

// ---------------- HMMA GEMM: g_hh = fp16(X @ W) --------------------
// 256 thr (8 warps), BM=128 (m16/warp), BN=DOUT, K=128 staged once.
// smem rows padded to 272B -> ldmatrix conflict-free (17*16B stride).
template <int DOUT, int XSEL>
__global__ void __launch_bounds__(256, 2) k_gemm_mma(const float* __restrict__ Xf) {
    constexpr int NT    = DOUT / 8;        // n-tiles per warp
    constexpr int ROWB  = 272;             // bytes per smem row (128 halfs + 8 pad)
    constexpr int A_SZ  = 128 * ROWB;      // 34816
    extern __shared__ char smem[];

    const int tid  = threadIdx.x;
    const int wid  = tid >> 5;
    const int lane = tid & 31;
    const int row0 = blockIdx.x * 128;

    // ---- fill A: 128 rows x 256B fp16 ----
    if (XSEL < 0) {
        for (int u = tid; u < 128 * 16; u += 256) {
            int row = u >> 4, k16 = u & 15;
            int r = row0 + row;
            float4 f0 = make_float4(0.f, 0.f, 0.f, 0.f), f1 = f0;
            if (r < NN) {
                const float4* xr = reinterpret_cast<const float4*>(&Xf[(size_t)r * DIN]);
                f0 = xr[k16 * 2];
                f1 = xr[k16 * 2 + 1];
            }
            __half2 h0 = __floats2half2_rn(f0.x, f0.y);
            __half2 h1 = __floats2half2_rn(f0.z, f0.w);
            __half2 h2 = __floats2half2_rn(f1.x, f1.y);
            __half2 h3 = __floats2half2_rn(f1.z, f1.w);
            uint4 pk;
            pk.x = *reinterpret_cast<uint32_t*>(&h0);
            pk.y = *reinterpret_cast<uint32_t*>(&h1);
            pk.z = *reinterpret_cast<uint32_t*>(&h2);
            pk.w = *reinterpret_cast<uint32_t*>(&h3);
            *reinterpret_cast<uint4*>(smem + row * ROWB + k16 * 16) = pk;
        }
    } else {
        const __half* Xh = bufh<(XSEL < 0) ? 1 : XSEL>();
        for (int u = tid; u < 128 * 16; u += 256) {
            int row = u >> 4, k16 = u & 15;
            int r = row0 + row;
            uint4 pk = make_uint4(0, 0, 0, 0);
            if (r < NN)
                pk = reinterpret_cast<const uint4*>(&Xh[(size_t)r * DIN])[k16];
            *reinterpret_cast<uint4*>(smem + row * ROWB + k16 * 16) = pk;
        }
    }
    // ---- fill B: DOUT rows x 256B from g_wt [n][k] ----
    {
        const __half* Wt = (DOUT == 64) ? g_wt2 : ((XSEL == 1) ? g_wt1 : g_wt0);
        for (int u = tid; u < DOUT * 16; u += 256) {
            int row = u >> 4, k16 = u & 15;
            uint4 pk = reinterpret_cast<const uint4*>(&Wt[(size_t)row * 128])[k16];
            *reinterpret_cast<uint4*>(smem + A_SZ + row * ROWB + k16 * 16) = pk;
        }
    }
    __syncthreads();

    uint32_t sbA = smem_u32(smem);
    uint32_t sbB = sbA + A_SZ;

    // per-lane ldmatrix base addresses
    int m_idx = lane >> 3;
    uint32_t a_base = sbA + (uint32_t)(wid * 16 + (m_idx & 1) * 8 + (lane & 7)) * ROWB
                          + (uint32_t)((m_idx >> 1) * 8) * 2;
    uint32_t b_rowoff = (uint32_t)(lane & 7) * ROWB + (uint32_t)(((lane >> 3) & 1) * 8) * 2;

    float acc[NT][4];
#pragma unroll
    for (int nt = 0; nt < NT; nt++)
#pragma unroll
        for (int j = 0; j < 4; j++) acc[nt][j] = 0.f;

#pragma unroll
    for (int kk = 0; kk < 8; kk++) {
        uint32_t a[4];
        ldsm_x4(a, a_base + kk * 32);
#pragma unroll
        for (int nt = 0; nt < NT; nt++) {
            uint32_t b[2];
            ldsm_x2(b, sbB + b_rowoff + (uint32_t)(nt * 8) * ROWB + kk * 32);
            mma16816(acc[nt], a, b);
        }
    }

    // ---- epilogue: fp16 pairs to g_hh ----
    int grp = lane >> 2, tig = lane & 3;
    int r0 = row0 + wid * 16 + grp;
    int r1 = r0 + 8;
#pragma unroll
    for (int nt = 0; nt < NT; nt++) {
        int col = nt * 8 + tig * 2;
        if (r0 < NN) {
            __half2 h = __floats2half2_rn(acc[nt][0], acc[nt][1]);
            *reinterpret_cast<uint32_t*>(&g_hh[(size_t)r0 * DOUT + col]) =
                *reinterpret_cast<uint32_t*>(&h);
        }
        if (r1 < NN) {
            __half2 h = __floats2half2_rn(acc[nt][2], acc[nt][3]);
            *reinterpret_cast<uint32_t*>(&g_hh[(size_t)r1 * DOUT + col]) =
                *reinterpret_cast<uint32_t*>(&h);
        }
    }
}

// ------- fused aggregate over fp16 H -> fp16 act (OSEL 1/2) or fp32 out (-1) ----
template <int DOUT, bool RELU, int OSEL>
__global__ void k_agg(const float* __restrict__ bias,
                      float* __restrict__ OUText) {
    int warp = (blockIdx.x * blockDim.x + threadIdx.x) >> 5;
    int lane = threadIdx.x & 31;
    if (warp >= NN) return;

    int beg = g_rowstart[warp];
    int end = g_rowstart[warp + 1];
    float din = g_deg[warp];
    float sn  = din * din;

    if (DOUT == 128) {
        const uint2* HH = reinterpret_cast<const uint2*>(g_hh);
        uint2 hr = HH[(size_t)warp * 32 + lane];
        float2 h01 = __half22float2(*reinterpret_cast<__half2*>(&hr.x));
        float2 h23 = __half22float2(*reinterpret_cast<__half2*>(&hr.y));
        float4 acc = make_float4(h01.x * sn, h01.y * sn, h23.x * sn, h23.y * sn);
        int e = beg;
        for (; e + 1 < end; e += 2) {
            Edge e0 = g_edge[e], e1 = g_edge[e + 1];
            uint2 r0 = HH[(size_t)e0.src * 32 + lane];
            uint2 r1 = HH[(size_t)e1.src * 32 + lane];
            float2 a01 = __half22float2(*reinterpret_cast<__half2*>(&r0.x));
            float2 a23 = __half22float2(*reinterpret_cast<__half2*>(&r0.y));
            float2 b01 = __half22float2(*reinterpret_cast<__half2*>(&r1.x));
            float2 b23 = __half22float2(*reinterpret_cast<__half2*>(&r1.y));
            acc.x += e0.nrm * a01.x + e1.nrm * b01.x;
            acc.y += e0.nrm * a01.y + e1.nrm * b01.y;
            acc.z += e0.nrm * a23.x + e1.nrm * b23.x;
            acc.w += e0.nrm * a23.y + e1.nrm * b23.y;
        }
        if (e < end) {
            Edge e0 = g_edge[e];
            uint2 r0 = HH[(size_t)e0.src * 32 + lane];
            float2 a01 = __half22float2(*reinterpret_cast<__half2*>(&r0.x));
            float2 a23 = __half22float2(*reinterpret_cast<__half2*>(&r0.y));
            acc.x += e0.nrm * a01.x; acc.y += e0.nrm * a01.y;
            acc.z += e0.nrm * a23.x; acc.w += e0.nrm * a23.y;
        }
        float4 bb = reinterpret_cast<const float4*>(bias)[lane];
        acc.x += bb.x; acc.y += bb.y; acc.z += bb.z; acc.w += bb.w;
        if (RELU) {
            acc.x = fmaxf(acc.x, 0.f); acc.y = fmaxf(acc.y, 0.f);
            acc.z = fmaxf(acc.z, 0.f); acc.w = fmaxf(acc.w, 0.f);
        }
        if (OSEL < 0) {
            reinterpret_cast<float4*>(OUText)[(size_t)warp * 32 + lane] = acc;
        } else {
            __half* outh = const_cast<__half*>(bufh<(OSEL < 0) ? 1 : OSEL>());
            __half2 o01 = __floats2half2_rn(acc.x, acc.y);
            __half2 o23 = __floats2half2_rn(acc.z, acc.w);
            uint2 pk;
            pk.x = *reinterpret_cast<uint32_t*>(&o01);
            pk.y = *reinterpret_cast<uint32_t*>(&o23);
            reinterpret_cast<uint2*>(outh)[(size_t)warp * 32 + lane] = pk;
        }
    } else {
        const __half2* HH = reinterpret_cast<const __half2*>(g_hh);
        float2 h = __half22float2(HH[(size_t)warp * 32 + lane]);
        float2 acc = make_float2(h.x * sn, h.y * sn);
        int e = beg;
        for (; e + 1 < end; e += 2) {
            Edge e0 = g_edge[e], e1 = g_edge[e + 1];
            float2 v0 = __half22float2(HH[(size_t)e0.src * 32 + lane]);
            float2 v1 = __half22float2(HH[(size_t)e1.src * 32 + lane]);
            acc.x += e0.nrm * v0.x + e1.nrm * v1.x;
            acc.y += e0.nrm * v0.y + e1.nrm * v1.y;
        }
        if (e < end) {
            Edge e0 = g_edge[e];
            float2 v = __half22float2(HH[(size_t)e0.src * 32 + lane]);
            acc.x += e0.nrm * v.x; acc.y += e0.nrm * v.y;
        }
        float2 bb = reinterpret_cast<const float2*>(bias)[lane];
        acc.x += bb.x; acc.y += bb.y;
        if (RELU) { acc.x = fmaxf(acc.x, 0.f); acc.y = fmaxf(acc.y, 0.f); }
        reinterpret_cast<float2*>(OUText)[(size_t)warp * 32 + lane] = acc;
    }
}

// ---------------- driver ----------------
extern "C" void kernel_launch(void* const* d_in, const int* in_sizes, int n_in,
                              void* d_out, int out_size) {
    const float* x  = (const float*)d_in[0];
    const int*   ei = (const int*)d_in[1];
    const float* ew = (const float*)d_in[2];
    const float* W0 = (const float*)d_in[3];
    const float* b0 = (const float*)d_in[4];
    const float* W1 = (const float*)d_in[5];
    const float* b1 = (const float*)d_in[6];
    const float* W2 = (const float*)d_in[7];
    const float* b2 = (const float*)d_in[8];
    float*       out = (float*)d_out;

    constexpr int SMEM_128 = 128 * 272 + 128 * 272;   // 69632
    constexpr int SMEM_64  = 128 * 272 + 64 * 272;    // 52224

    static cudaStream_t s2 = nullptr;
    static cudaEvent_t  ev_fork = nullptr, ev_join = nullptr;
    static bool tried = false;
    if (!tried) {
        tried = true;
        if (cudaStreamCreateWithFlags(&s2, cudaStreamNonBlocking) != cudaSuccess) s2 = nullptr;
        if (cudaEventCreateWithFlags(&ev_fork, cudaEventDisableTiming) != cudaSuccess) ev_fork = nullptr;
        if (cudaEventCreateWithFlags(&ev_join, cudaEventDisableTiming) != cudaSuccess) ev_join = nullptr;
        cudaFuncSetAttribute(k_gemm_mma<128, -1>, cudaFuncAttributeMaxDynamicSharedMemorySize, SMEM_128);
        cudaFuncSetAttribute(k_gemm_mma<128,  1>, cudaFuncAttributeMaxDynamicSharedMemorySize, SMEM_128);
        cudaFuncSetAttribute(k_gemm_mma<64,   2>, cudaFuncAttributeMaxDynamicSharedMemorySize, SMEM_64);
    }
    const bool fork = (s2 && ev_fork && ev_join);
    cudaStream_t sp = fork ? s2 : (cudaStream_t)0;

    const int T = 256;
    if (fork) {
        cudaEventRecord(ev_fork, 0);
        cudaStreamWaitEvent(s2, ev_fork, 0);
    }
    // CSR preamble (independent of GEMM0)
    k_init<<<(NN + T - 1) / T, T, 0, sp>>>();
    k_deg_acc<<<(NE / 4 + T - 1) / T, T, 0, sp>>>(ei, ew);
    k_scan_a<<<NBLK, 256, 0, sp>>>();
    k_scan_b<<<1, 128, 0, sp>>>();
    k_scan_c<<<NBLK, 256, 0, sp>>>();
    k_bucket<<<(NE / 4 + T - 1) / T, T, 0, sp>>>(ei, ew);
    if (fork) cudaEventRecord(ev_join, s2);

    const int gemm_blocks = (NN + 127) / 128;   // 782
    const int agg_blocks  = (NN * 32 + T - 1) / T;

    // weights -> transposed fp16 (needed by GEMM0 immediately)
    k_wconv<<<64, 256>>>(W0, W1, W2);

    // layer 0 GEMM overlaps the preamble
    k_gemm_mma<128, -1><<<gemm_blocks, 256, SMEM_128>>>(x);
    if (fork) cudaStreamWaitEvent(0, ev_join, 0);
    k_agg<128, true, 1><<<agg_blocks, T>>>(b0, nullptr);

    // layer 1
    k_gemm_mma<128, 1><<<gemm_blocks, 256, SMEM_128>>>(nullptr);
    k_agg<128, true, 2><<<agg_blocks, T>>>(b1, nullptr);

    // layer 2
    k_gemm_mma<64, 2><<<gemm_blocks, 256, SMEM_64>>>(nullptr);
    k_agg<64, false, -1><<<agg_blocks, T>>>(b2, out);
}